// round 6
// baseline (speedup 1.0000x reference)
#include <cuda_runtime.h>
#include <float.h>

#define NNODES 100000
#define F_IN   128
#define D1     256      // 8 heads * 32
#define HEADS  8
#define NCLS   40
#define NEG    0.2f
#define EMAX   1600000
#define SCAN_B 1024

// ---------------- scratch (device globals; no allocation allowed) ----------
__device__ __align__(16) float g_h1[NNODES * D1];      // x @ W1
__device__ __align__(16) float g_h2[NNODES * D1];      // layer-1 output
__device__ float g_ssrc1[NNODES * HEADS];
__device__ float g_sdst1[NNODES * HEADS];
__device__ float g_pself1[NNODES * HEADS];
__device__ __align__(16) float g_h3[NNODES * NCLS];    // h2 @ W2
__device__ float g_ssrc2[NNODES];
__device__ float g_sdst2[NNODES];
__device__ float g_pself2[NNODES];
// CSR (dst-binned edges)
__device__ int g_counts[NNODES];
__device__ int g_rowptr[NNODES + 1];
__device__ int g_cursor[NNODES];
__device__ int g_csr_src[EMAX];
__device__ int g_bsum[(NNODES + SCAN_B - 1) / SCAN_B];
__device__ int g_boff[(NNODES + SCAN_B - 1) / SCAN_B];

__device__ __forceinline__ float lrelu(float v) { return v >= 0.f ? v : NEG * v; }

// ======================= CSR build ==========================================
__global__ __launch_bounds__(256) void zero_counts_kernel(int n) {
    int i = blockIdx.x * blockDim.x + threadIdx.x;
    if (i < n) g_counts[i] = 0;
}

__global__ __launch_bounds__(256) void hist_kernel(const int* __restrict__ dst, int E) {
    int e = blockIdx.x * blockDim.x + threadIdx.x;
    if (e < E) atomicAdd(&g_counts[dst[e]], 1);
}

__global__ __launch_bounds__(SCAN_B) void scan_sums_kernel(int n) {
    __shared__ int ws[32];
    int i = blockIdx.x * SCAN_B + threadIdx.x;
    int v = (i < n) ? g_counts[i] : 0;
    int lane = threadIdx.x & 31, w = threadIdx.x >> 5;
    int s = v;
#pragma unroll
    for (int o = 16; o; o >>= 1) s += __shfl_xor_sync(0xffffffffu, s, o);
    if (lane == 0) ws[w] = s;
    __syncthreads();
    if (w == 0) {
        int t = ws[lane];
#pragma unroll
        for (int o = 16; o; o >>= 1) t += __shfl_xor_sync(0xffffffffu, t, o);
        if (lane == 0) g_bsum[blockIdx.x] = t;
    }
}

__global__ __launch_bounds__(SCAN_B) void scan_offsets_kernel(int nb, int n) {
    __shared__ int ws[32];
    int lane = threadIdx.x & 31, w = threadIdx.x >> 5;
    int v = (threadIdx.x < nb) ? g_bsum[threadIdx.x] : 0;
    int x = v;
#pragma unroll
    for (int o = 1; o < 32; o <<= 1) {
        int y = __shfl_up_sync(0xffffffffu, x, o);
        if (lane >= o) x += y;
    }
    if (lane == 31) ws[w] = x;
    __syncthreads();
    if (w == 0) {
        int s = ws[lane];
#pragma unroll
        for (int o = 1; o < 32; o <<= 1) {
            int y = __shfl_up_sync(0xffffffffu, s, o);
            if (lane >= o) s += y;
        }
        ws[lane] = s;
    }
    __syncthreads();
    int incl = x + (w > 0 ? ws[w - 1] : 0);
    if (threadIdx.x < nb) g_boff[threadIdx.x] = incl - v;
    if (threadIdx.x == nb - 1) g_rowptr[n] = incl;
}

__global__ __launch_bounds__(SCAN_B) void scan_apply_kernel(int n) {
    __shared__ int ws[32];
    int i = blockIdx.x * SCAN_B + threadIdx.x;
    int v = (i < n) ? g_counts[i] : 0;
    int lane = threadIdx.x & 31, w = threadIdx.x >> 5;
    int x = v;
#pragma unroll
    for (int o = 1; o < 32; o <<= 1) {
        int y = __shfl_up_sync(0xffffffffu, x, o);
        if (lane >= o) x += y;
    }
    if (lane == 31) ws[w] = x;
    __syncthreads();
    if (w == 0) {
        int s = ws[lane];
#pragma unroll
        for (int o = 1; o < 32; o <<= 1) {
            int y = __shfl_up_sync(0xffffffffu, s, o);
            if (lane >= o) s += y;
        }
        ws[lane] = s;
    }
    __syncthreads();
    int excl = x - v + (w > 0 ? ws[w - 1] : 0) + g_boff[blockIdx.x];
    if (i < n) { g_rowptr[i] = excl; g_cursor[i] = excl; }
}

__global__ __launch_bounds__(256) void scatter_kernel(const int* __restrict__ src,
                                                      const int* __restrict__ dst, int E) {
    int e = blockIdx.x * blockDim.x + threadIdx.x;
    if (e >= E) return;
    int pos = atomicAdd(&g_cursor[dst[e]], 1);
    g_csr_src[pos] = src[e];
}

// ======== GEMM1 + fused scores: h1 = x@W1; also s_src/s_dst/p_self ==========
#define TM 64
#define TN 64
#define TK 16
#define APAD 8   // 16B-aligned smem rows -> LDS.128

__global__ __launch_bounds__(256) void gemm1_kernel(const float* __restrict__ A,
                                                    const float* __restrict__ B,
                                                    const float* __restrict__ asrc,
                                                    const float* __restrict__ adst,
                                                    int M) {
    __shared__ float As[TK][TM + APAD];
    __shared__ float Bs[TK][TN + APAD];
    __shared__ float sS[TM][2];
    __shared__ float sD[TM][2];
    int tid = threadIdx.x;
    int tx = tid & 15, ty = tid >> 4;
    int rowBase = blockIdx.y * TM;
    int colBase = blockIdx.x * TN;
    float acc[4][4] = {};

    if (tid < TM) { sS[tid][0] = 0.f; sS[tid][1] = 0.f; sD[tid][0] = 0.f; sD[tid][1] = 0.f; }

    for (int k0 = 0; k0 < F_IN; k0 += TK) {
        {
            int r  = tid >> 2;
            int kg = (tid & 3) * 4;
            float4 v = make_float4(0.f, 0.f, 0.f, 0.f);
            int gr = rowBase + r;
            if (gr < M) v = *(const float4*)&A[(size_t)gr * F_IN + k0 + kg];
            As[kg + 0][r] = v.x; As[kg + 1][r] = v.y;
            As[kg + 2][r] = v.z; As[kg + 3][r] = v.w;
        }
        {
            int kk = tid >> 4;
            int c  = (tid & 15) * 4;
            float4 v = *(const float4*)&B[(size_t)(k0 + kk) * D1 + colBase + c];
            *(float4*)&Bs[kk][c] = v;
        }
        __syncthreads();
#pragma unroll
        for (int kk = 0; kk < TK; kk++) {
            float4 a = *(const float4*)&As[kk][ty * 4];
            float4 b = *(const float4*)&Bs[kk][tx * 4];
            acc[0][0] += a.x * b.x; acc[0][1] += a.x * b.y; acc[0][2] += a.x * b.z; acc[0][3] += a.x * b.w;
            acc[1][0] += a.y * b.x; acc[1][1] += a.y * b.y; acc[1][2] += a.y * b.z; acc[1][3] += a.y * b.w;
            acc[2][0] += a.z * b.x; acc[2][1] += a.z * b.y; acc[2][2] += a.z * b.z; acc[2][3] += a.z * b.w;
            acc[3][0] += a.w * b.x; acc[3][1] += a.w * b.y; acc[3][2] += a.w * b.z; acc[3][3] += a.w * b.w;
        }
        __syncthreads();
    }
#pragma unroll
    for (int i = 0; i < 4; i++) {
        int gr = rowBase + ty * 4 + i;
        if (gr < M) {
            float4 o = make_float4(acc[i][0], acc[i][1], acc[i][2], acc[i][3]);
            *(float4*)&g_h1[(size_t)gr * D1 + colBase + tx * 4] = o;
        }
    }
    float4 av = *(const float4*)&asrc[colBase + tx * 4];
    float4 dv = *(const float4*)&adst[colBase + tx * 4];
    int hh = tx >> 3;
#pragma unroll
    for (int i = 0; i < 4; i++) {
        float ps = acc[i][0]*av.x + acc[i][1]*av.y + acc[i][2]*av.z + acc[i][3]*av.w;
        float pd = acc[i][0]*dv.x + acc[i][1]*dv.y + acc[i][2]*dv.z + acc[i][3]*dv.w;
        atomicAdd(&sS[ty * 4 + i][hh], ps);
        atomicAdd(&sD[ty * 4 + i][hh], pd);
    }
    __syncthreads();
    if (tid < 2 * TM) {
        int row = tid >> 1, h2i = tid & 1;
        int gr = rowBase + row;
        if (gr < M) {
            int head = blockIdx.x * 2 + h2i;
            float ps = sS[row][h2i], pd = sD[row][h2i];
            g_ssrc1[gr * HEADS + head] = ps;
            g_sdst1[gr * HEADS + head] = pd;
            g_pself1[gr * HEADS + head] = __expf(lrelu(ps + pd));
        }
    }
}

// ======== aggregate1: 2 warps/node (128 ch each), CSR, unroll-4 =============
__global__ __launch_bounds__(256) void aggregate1_kernel(const float* __restrict__ b1, int M) {
    int gw   = (blockIdx.x * blockDim.x + threadIdx.x) >> 5;
    int node = gw >> 1;
    int half = gw & 1;
    int lane = threadIdx.x & 31;
    if (node >= M) return;
    int ch = half * 128 + lane * 4;
    int h  = ch >> 5;
    float sdst_h = g_sdst1[node * HEADS + h];
    float pself  = g_pself1[node * HEADS + h];
    size_t nb = (size_t)node * D1 + ch;
    float4 a = *(const float4*)&g_h1[nb];
    float c0 = a.x * pself, c1 = a.y * pself, c2 = a.z * pself, c3 = a.w * pself;
    float denom = pself;
    int beg = g_rowptr[node], end = g_rowptr[node + 1];
    int i = beg;
    for (; i + 4 <= end; i += 4) {
        int s0 = __ldg(&g_csr_src[i]);
        int s1 = __ldg(&g_csr_src[i + 1]);
        int s2 = __ldg(&g_csr_src[i + 2]);
        int s3 = __ldg(&g_csr_src[i + 3]);
        float e0 = __ldg(&g_ssrc1[s0 * HEADS + h]);
        float e1 = __ldg(&g_ssrc1[s1 * HEADS + h]);
        float e2 = __ldg(&g_ssrc1[s2 * HEADS + h]);
        float e3 = __ldg(&g_ssrc1[s3 * HEADS + h]);
        float4 v0 = *(const float4*)&g_h1[(size_t)s0 * D1 + ch];
        float4 v1 = *(const float4*)&g_h1[(size_t)s1 * D1 + ch];
        float4 v2 = *(const float4*)&g_h1[(size_t)s2 * D1 + ch];
        float4 v3 = *(const float4*)&g_h1[(size_t)s3 * D1 + ch];
        float p0 = __expf(lrelu(e0 + sdst_h));
        float p1 = __expf(lrelu(e1 + sdst_h));
        float p2 = __expf(lrelu(e2 + sdst_h));
        float p3 = __expf(lrelu(e3 + sdst_h));
        c0 += v0.x * p0 + v1.x * p1 + v2.x * p2 + v3.x * p3;
        c1 += v0.y * p0 + v1.y * p1 + v2.y * p2 + v3.y * p3;
        c2 += v0.z * p0 + v1.z * p1 + v2.z * p2 + v3.z * p3;
        c3 += v0.w * p0 + v1.w * p1 + v2.w * p2 + v3.w * p3;
        denom += (p0 + p1) + (p2 + p3);
    }
    for (; i < end; i++) {
        int s = __ldg(&g_csr_src[i]);
        float p = __expf(lrelu(__ldg(&g_ssrc1[s * HEADS + h]) + sdst_h));
        float4 v = *(const float4*)&g_h1[(size_t)s * D1 + ch];
        c0 += v.x * p; c1 += v.y * p; c2 += v.z * p; c3 += v.w * p;
        denom += p;
    }
    float inv = __frcp_rn(denom);
    float4 bb = *(const float4*)&b1[ch];
    float4 o;
    o.x = fmaxf(c0 * inv + bb.x, 0.f);
    o.y = fmaxf(c1 * inv + bb.y, 0.f);
    o.z = fmaxf(c2 * inv + bb.z, 0.f);
    o.w = fmaxf(c3 * inv + bb.w, 0.f);
    *(float4*)&g_h2[nb] = o;
}

// ======== GEMM2 + fused scores2: h3 = h2@W2; s_src2/s_dst2/p_self2 =========
__global__ __launch_bounds__(256) void gemm2_kernel(const float* __restrict__ B,
                                                    const float* __restrict__ asrc,
                                                    const float* __restrict__ adst,
                                                    int M) {
    __shared__ float Bs[D1 * NCLS];  // 40 KB
    for (int i = threadIdx.x; i < D1 * NCLS; i += 256) Bs[i] = B[i];
    __syncthreads();
    int warp = threadIdx.x >> 5, lane = threadIdx.x & 31;
    float as0 = asrc[lane], ad0 = adst[lane];
    float as1 = (lane < 8) ? asrc[32 + lane] : 0.f;
    float ad1 = (lane < 8) ? adst[32 + lane] : 0.f;
    const int RPW = 16;
    int rowBase = (blockIdx.x * 8 + warp) * RPW;
    for (int i = 0; i < RPW; i++) {
        int row = rowBase + i;
        if (row >= M) return;
        const float* a = &g_h2[(size_t)row * D1];
        float acc0 = 0.f, acc1 = 0.f;
#pragma unroll 4
        for (int k = 0; k < D1; k += 4) {
            float4 av = *(const float4*)(a + k);
            acc0 += av.x * Bs[(k + 0) * NCLS + lane];
            acc0 += av.y * Bs[(k + 1) * NCLS + lane];
            acc0 += av.z * Bs[(k + 2) * NCLS + lane];
            acc0 += av.w * Bs[(k + 3) * NCLS + lane];
            if (lane < 8) {
                acc1 += av.x * Bs[(k + 0) * NCLS + 32 + lane];
                acc1 += av.y * Bs[(k + 1) * NCLS + 32 + lane];
                acc1 += av.z * Bs[(k + 2) * NCLS + 32 + lane];
                acc1 += av.w * Bs[(k + 3) * NCLS + 32 + lane];
            }
        }
        g_h3[(size_t)row * NCLS + lane] = acc0;
        if (lane < 8) g_h3[(size_t)row * NCLS + 32 + lane] = acc1;
        float ps = acc0 * as0 + ((lane < 8) ? acc1 * as1 : 0.f);
        float pd = acc0 * ad0 + ((lane < 8) ? acc1 * ad1 : 0.f);
#pragma unroll
        for (int o = 16; o; o >>= 1) {
            ps += __shfl_xor_sync(0xffffffffu, ps, o);
            pd += __shfl_xor_sync(0xffffffffu, pd, o);
        }
        if (lane == 0) {
            g_ssrc2[row] = ps;
            g_sdst2[row] = pd;
            g_pself2[row] = __expf(lrelu(ps + pd));
        }
    }
}

// ======== aggregate2: node-per-warp, CSR, unroll-4, fused log_softmax ======
__global__ __launch_bounds__(256) void aggregate2_kernel(const float* __restrict__ b2,
                                                         float* __restrict__ out, int M) {
    int wid  = (blockIdx.x * blockDim.x + threadIdx.x) >> 5;
    int lane = threadIdx.x & 31;
    if (wid >= M) return;
    float sdst = g_sdst2[wid];
    float pself = g_pself2[wid];
    size_t nb = (size_t)wid * NCLS;
    float v0 = g_h3[nb + lane] * pself;
    float v1 = (lane < 8) ? g_h3[nb + 32 + lane] * pself : 0.f;
    float denom = pself;
    int beg = g_rowptr[wid], end = g_rowptr[wid + 1];
    int i = beg;
    for (; i + 4 <= end; i += 4) {
        int s0 = __ldg(&g_csr_src[i]);
        int s1 = __ldg(&g_csr_src[i + 1]);
        int s2 = __ldg(&g_csr_src[i + 2]);
        int s3 = __ldg(&g_csr_src[i + 3]);
        float e0 = __ldg(&g_ssrc2[s0]);
        float e1 = __ldg(&g_ssrc2[s1]);
        float e2 = __ldg(&g_ssrc2[s2]);
        float e3 = __ldg(&g_ssrc2[s3]);
        float q0 = g_h3[(size_t)s0 * NCLS + lane];
        float q1 = g_h3[(size_t)s1 * NCLS + lane];
        float q2 = g_h3[(size_t)s2 * NCLS + lane];
        float q3 = g_h3[(size_t)s3 * NCLS + lane];
        float p0 = __expf(lrelu(e0 + sdst));
        float p1 = __expf(lrelu(e1 + sdst));
        float p2 = __expf(lrelu(e2 + sdst));
        float p3 = __expf(lrelu(e3 + sdst));
        v0 += q0 * p0 + q1 * p1 + q2 * p2 + q3 * p3;
        if (lane < 8) {
            v1 += p0 * g_h3[(size_t)s0 * NCLS + 32 + lane]
                + p1 * g_h3[(size_t)s1 * NCLS + 32 + lane]
                + p2 * g_h3[(size_t)s2 * NCLS + 32 + lane]
                + p3 * g_h3[(size_t)s3 * NCLS + 32 + lane];
        }
        denom += (p0 + p1) + (p2 + p3);
    }
    for (; i < end; i++) {
        int s = __ldg(&g_csr_src[i]);
        float p = __expf(lrelu(__ldg(&g_ssrc2[s]) + sdst));
        size_t sb = (size_t)s * NCLS;
        v0 += p * g_h3[sb + lane];
        if (lane < 8) v1 += p * g_h3[sb + 32 + lane];
        denom += p;
    }
    float inv = __frcp_rn(denom);
    float z0 = v0 * inv + b2[lane];
    float z1 = (lane < 8) ? (v1 * inv + b2[32 + lane]) : -FLT_MAX;
    float m = fmaxf(z0, z1);
#pragma unroll
    for (int o = 16; o; o >>= 1) m = fmaxf(m, __shfl_xor_sync(0xffffffffu, m, o));
    float s = expf(z0 - m) + ((lane < 8) ? expf(z1 - m) : 0.f);
#pragma unroll
    for (int o = 16; o; o >>= 1) s += __shfl_xor_sync(0xffffffffu, s, o);
    float ls = logf(s);
    out[nb + lane] = z0 - m - ls;
    if (lane < 8) out[nb + 32 + lane] = z1 - m - ls;
}

// ---------------------------------------------------------------------------
extern "C" void kernel_launch(void* const* d_in, const int* in_sizes, int n_in,
                              void* d_out, int out_size) {
    const float* x     = (const float*)d_in[0];
    const int*   ei    = (const int*)d_in[1];      // JAX x64 disabled -> int32
    const float* W1    = (const float*)d_in[2];
    const float* asrc1 = (const float*)d_in[3];
    const float* adst1 = (const float*)d_in[4];
    const float* b1    = (const float*)d_in[5];
    const float* W2    = (const float*)d_in[6];
    const float* asrc2 = (const float*)d_in[7];
    const float* adst2 = (const float*)d_in[8];
    const float* b2    = (const float*)d_in[9];
    float* out = (float*)d_out;

    int M = in_sizes[0] / F_IN;        // 100000
    int E = in_sizes[1] / 2;           // 1600000
    const int* src = ei;
    const int* dst = ei + E;
    int NB = (M + SCAN_B - 1) / SCAN_B;

    // CSR build
    zero_counts_kernel<<<(M + 255) / 256, 256>>>(M);
    hist_kernel<<<(E + 255) / 256, 256>>>(dst, E);
    scan_sums_kernel<<<NB, SCAN_B>>>(M);
    scan_offsets_kernel<<<1, SCAN_B>>>(NB, M);
    scan_apply_kernel<<<NB, SCAN_B>>>(M);
    scatter_kernel<<<(E + 255) / 256, 256>>>(src, dst, E);

    // Layer 1
    {
        dim3 grid(D1 / TN, (M + TM - 1) / TM);
        gemm1_kernel<<<grid, 256>>>(x, W1, asrc1, adst1, M);
    }
    aggregate1_kernel<<<(M * 64 + 255) / 256, 256>>>(b1, M);

    // Layer 2
    gemm2_kernel<<<(M + 127) / 128, 256>>>(W2, asrc2, adst2, M);
    aggregate2_kernel<<<(M * 32 + 255) / 256, 256>>>(b2, out, M);
}